// round 5
// baseline (speedup 1.0000x reference)
#include <cuda_runtime.h>

#define DD 128        // input dim
#define UU 128        // units
#define BT 64         // batch rows per block
#define DK 16         // d-chunk
#define CLIPV 20.0f
#define EPSV 1e-7f

// Preprocessed weights (device globals: no allocation allowed)
__device__ float gW1[DD * UU];   // tanh(w_hat)*sigmoid(m_hat), [d][u]
__device__ float gW2[DD * UU];   // tanh(w_hat')*sigmoid(m_hat'), [d][u]
__device__ float gA [DD * UU];   // |W2^T| : gA[d][u] = |W2[u][d]| (sign-path factor)

// ---------- packed f32x2 helpers (Blackwell sm_103a) ----------
__device__ __forceinline__ unsigned long long pack2(float lo, float hi) {
    unsigned long long r;
    asm("mov.b64 %0, {%1, %2};" : "=l"(r) : "f"(lo), "f"(hi));
    return r;
}
__device__ __forceinline__ void unpack2(unsigned long long v, float& lo, float& hi) {
    asm("mov.b64 {%0, %1}, %2;" : "=f"(lo), "=f"(hi) : "l"(v));
}
__device__ __forceinline__ unsigned long long fma2(unsigned long long a,
                                                   unsigned long long b,
                                                   unsigned long long c) {
    unsigned long long d;
    asm("fma.rn.f32x2 %0, %1, %2, %3;" : "=l"(d) : "l"(a), "l"(b), "l"(c));
    return d;
}
__device__ __forceinline__ unsigned long long mul2(unsigned long long a,
                                                   unsigned long long b) {
    unsigned long long d;
    asm("mul.rn.f32x2 %0, %1, %2;" : "=l"(d) : "l"(a), "l"(b));
    return d;
}

__device__ __forceinline__ float sigm(float z) {
    return 1.0f / (1.0f + __expf(-z));
}

// ---------- prep: build W1, W2, |W2^T| ----------
__global__ void nalu_prep(const float* __restrict__ w_hat,
                          const float* __restrict__ m_hat,
                          const float* __restrict__ w_hat_p,
                          const float* __restrict__ m_hat_p) {
    int i = blockIdx.x * blockDim.x + threadIdx.x;
    if (i >= DD * UU) return;
    float w1 = tanhf(w_hat[i])   * sigm(m_hat[i]);
    float w2 = tanhf(w_hat_p[i]) * sigm(m_hat_p[i]);
    gW1[i] = w1;
    gW2[i] = w2;
    int r = i / UU;   // original row (D index)
    int c = i % UU;   // original col (U index)
    // sign path uses |w2[u, d]| for output u, inner d  ->  gA[d=c_ofA?]
    // gA laid out d-major like gW*: gA[d][u] = |w2[u][d]| -> write at [c][r]
    gA[c * UU + r] = fabsf(w2);
}

// ---------- main fused kernel ----------
__global__ __launch_bounds__(256, 1)
void nalu_main(const float* __restrict__ x,
               const float* __restrict__ g,
               float* __restrict__ out) {
    // x-side chunk, transposed [d][b] for broadcast reads (row = 68 floats keeps 16B align)
    __shared__ __align__(16) float sx[DK][BT + 4];
    __shared__ __align__(16) float sl[DK][BT + 4];
    __shared__ __align__(16) float ss[DK][BT + 4];
    // weight chunks, [d][u]
    __shared__ __align__(16) float sw1[DK][UU];
    __shared__ __align__(16) float sw2[DK][UU];
    __shared__ __align__(16) float sa [DK][UU];

    const int tid  = threadIdx.x;
    const int tx   = tid & 15;        // u group: 16 groups of 8 u
    const int ty   = tid >> 4;        // b group: 16 groups of 4 b
    const int b0   = blockIdx.x * BT;
    const int u0   = tx * 8;
    const int brow = ty * 4;

    const int lrow = tid >> 2;        // 0..63 load row
    const int lq   = tid & 3;         // 0..3 load quad (4 floats each over DK=16)

    const unsigned long long one2 = pack2(1.0f, 1.0f);

    unsigned long long a2[4][4], t2[4][4], p2[4][4];
#pragma unroll
    for (int i = 0; i < 4; i++)
#pragma unroll
        for (int j = 0; j < 4; j++) {
            a2[i][j] = 0ull;          // {0.0f, 0.0f}
            t2[i][j] = 0ull;
            p2[i][j] = one2;
        }

    for (int d0 = 0; d0 < DD; d0 += DK) {
        __syncthreads();   // previous chunk's readers done before overwrite

        // ---- load x chunk (64 rows x 16 d), derive log|x| and sign-1, store transposed
        {
            const float4 v = *reinterpret_cast<const float4*>(
                &x[(b0 + lrow) * DD + d0 + lq * 4]);
            float vv[4] = {v.x, v.y, v.z, v.w};
#pragma unroll
            for (int k = 0; k < 4; k++) {
                float xv = vv[k];
                int dd = lq * 4 + k;
                sx[dd][lrow] = xv;
                sl[dd][lrow] = __logf(fmaxf(fabsf(xv), EPSV));
                // sign(x) - 1 : {+1->0, 0->-1, -1->-2}
                float sm1 = (xv > 0.0f) ? 0.0f : ((xv < 0.0f) ? -2.0f : -1.0f);
                ss[dd][lrow] = sm1;
            }
        }
        // ---- load weight chunks (16 rows x 128 u, three matrices)
        {
#pragma unroll
            for (int k = 0; k < 2; k++) {
                int f  = tid + 256 * k;        // 0..511 (512 float4 per matrix)
                int r  = f >> 5;               // 0..15
                int c4 = (f & 31) << 2;        // 0..124
                int gi = (d0 + r) * UU + c4;
                *reinterpret_cast<float4*>(&sw1[r][c4]) =
                    *reinterpret_cast<const float4*>(&gW1[gi]);
                *reinterpret_cast<float4*>(&sw2[r][c4]) =
                    *reinterpret_cast<const float4*>(&gW2[gi]);
                *reinterpret_cast<float4*>(&sa[r][c4]) =
                    *reinterpret_cast<const float4*>(&gA[gi]);
            }
        }
        __syncthreads();

        // ---- compute
#pragma unroll
        for (int dd = 0; dd < DK; dd++) {
            float4 xv = *reinterpret_cast<const float4*>(&sx[dd][brow]);
            float4 lv = *reinterpret_cast<const float4*>(&sl[dd][brow]);
            float4 sv = *reinterpret_cast<const float4*>(&ss[dd][brow]);

            unsigned long long w1p[4], w2p[4], ap[4];
            {
                const ulonglong2* q = reinterpret_cast<const ulonglong2*>(&sw1[dd][u0]);
                ulonglong2 v0 = q[0], v1 = q[1];
                w1p[0] = v0.x; w1p[1] = v0.y; w1p[2] = v1.x; w1p[3] = v1.y;
            }
            {
                const ulonglong2* q = reinterpret_cast<const ulonglong2*>(&sw2[dd][u0]);
                ulonglong2 v0 = q[0], v1 = q[1];
                w2p[0] = v0.x; w2p[1] = v0.y; w2p[2] = v1.x; w2p[3] = v1.y;
            }
            {
                const ulonglong2* q = reinterpret_cast<const ulonglong2*>(&sa[dd][u0]);
                ulonglong2 v0 = q[0], v1 = q[1];
                ap[0] = v0.x; ap[1] = v0.y; ap[2] = v1.x; ap[3] = v1.y;
            }

            float xs[4] = {xv.x, xv.y, xv.z, xv.w};
            float ls[4] = {lv.x, lv.y, lv.z, lv.w};
            float vs[4] = {sv.x, sv.y, sv.z, sv.w};

#pragma unroll
            for (int i = 0; i < 4; i++) {
                unsigned long long xb = pack2(xs[i], xs[i]);
                unsigned long long lb = pack2(ls[i], ls[i]);
                unsigned long long sb = pack2(vs[i], vs[i]);
#pragma unroll
                for (int j = 0; j < 4; j++) {
                    a2[i][j] = fma2(xb, w1p[j], a2[i][j]);
                    t2[i][j] = fma2(lb, w2p[j], t2[i][j]);
                    p2[i][j] = mul2(p2[i][j], fma2(sb, ap[j], one2));
                }
            }
        }
    }

    // ---- epilogue: out = g1*a1 + (1-g1)*exp(min(t,CLIP))*clamp(p,-1,1)
    float g1[8];
#pragma unroll
    for (int j = 0; j < 8; j++)
        g1[j] = sigm(__ldg(&g[u0 + j]));

#pragma unroll
    for (int i = 0; i < 4; i++) {
        float res[8];
#pragma unroll
        for (int j = 0; j < 4; j++) {
            float alo, ahi, tlo, thi, plo, phi;
            unpack2(a2[i][j], alo, ahi);
            unpack2(t2[i][j], tlo, thi);
            unpack2(p2[i][j], plo, phi);

            float m1lo = __expf(fminf(tlo, CLIPV));
            float m1hi = __expf(fminf(thi, CLIPV));
            float mslo = fminf(fmaxf(plo, -1.0f), 1.0f);
            float mshi = fminf(fmaxf(phi, -1.0f), 1.0f);

            float glo = g1[2 * j], ghi = g1[2 * j + 1];
            res[2 * j]     = glo * alo + (1.0f - glo) * m1lo * mslo;
            res[2 * j + 1] = ghi * ahi + (1.0f - ghi) * m1hi * mshi;
        }
        int b = b0 + brow + i;
        float4* o = reinterpret_cast<float4*>(&out[b * UU + u0]);
        o[0] = make_float4(res[0], res[1], res[2], res[3]);
        o[1] = make_float4(res[4], res[5], res[6], res[7]);
    }
}

extern "C" void kernel_launch(void* const* d_in, const int* in_sizes, int n_in,
                              void* d_out, int out_size) {
    const float* x        = (const float*)d_in[0];
    const float* w_hat    = (const float*)d_in[1];
    const float* m_hat    = (const float*)d_in[2];
    const float* w_hat_p  = (const float*)d_in[3];
    const float* m_hat_p  = (const float*)d_in[4];
    const float* g        = (const float*)d_in[5];
    float* out            = (float*)d_out;

    int B = in_sizes[0] / DD;   // 8192

    nalu_prep<<<(DD * UU + 255) / 256, 256>>>(w_hat, m_hat, w_hat_p, m_hat_p);
    nalu_main<<<B / BT, 256>>>(x, g, out);
}